// round 5
// baseline (speedup 1.0000x reference)
#include <cuda_runtime.h>

#define NN 50000
#define DD 128
#define EE 800000

// ---- scratch (__device__ globals: allocation-free) ----
__device__ int   g_cntrow[NN];     // degree over row (for CSR)
__device__ int   g_degcol[NN];     // degree over col (for norm)
__device__ int   g_off[NN + 1];    // CSR row offsets
__device__ int   g_cursor[NN];     // scatter cursors
__device__ int   g_scol[EE];       // edges sorted by row: col ids
__device__ float g_dis[NN];        // deg_col^-0.5 (0 if deg==0)
__device__ unsigned int g_maxbits; // ordered-float max; zero-init == -inf encoding,
                                   // atomicMax idempotent across graph replays
__device__ float2 g_ppM;           // (pp, M = pp*max(x))

__device__ __forceinline__ unsigned int ford(float f) {
    unsigned int b = __float_as_uint(f);
    return (b & 0x80000000u) ? ~b : (b | 0x80000000u);
}
__device__ __forceinline__ float funord(unsigned int u) {
    unsigned int b = (u & 0x80000000u) ? (u & 0x7FFFFFFFu) : ~u;
    return __uint_as_float(b);
}

// L1: zero counters AND global max of x (proven fine in R3/R4)
__global__ void k_zero_max(const float* __restrict__ x) {
    const int gsz = gridDim.x * blockDim.x;
    int gi = blockIdx.x * blockDim.x + threadIdx.x;
    for (int i = gi; i < NN; i += gsz) { g_cntrow[i] = 0; g_degcol[i] = 0; }

    float m = -3.402823466e38f;
    const float4* x4 = (const float4*)x;
    const int n4 = (NN * DD) / 4;
    for (int i = gi; i < n4; i += gsz) {
        float4 v = x4[i];
        m = fmaxf(m, fmaxf(fmaxf(v.x, v.y), fmaxf(v.z, v.w)));
    }
#pragma unroll
    for (int o = 16; o; o >>= 1) m = fmaxf(m, __shfl_xor_sync(~0u, m, o));
    __shared__ float sm[32];
    int lane = threadIdx.x & 31, w = threadIdx.x >> 5;
    if (lane == 0) sm[w] = m;
    __syncthreads();
    if (w == 0) {
        m = (lane < (int)(blockDim.x >> 5)) ? sm[lane] : -3.402823466e38f;
#pragma unroll
        for (int o = 16; o; o >>= 1) m = fmaxf(m, __shfl_xor_sync(~0u, m, o));
        if (lane == 0) atomicMax(&g_maxbits, ford(m));
    }
}

// L2: histogram degrees — EXACT R2 shape (1 edge/thread)
__global__ void k_count(const int* __restrict__ ei) {
    int e = blockIdx.x * blockDim.x + threadIdx.x;
    if (e < EE) {
        int r = ei[e];
        int c = ei[EE + e];
        atomicAdd(&g_cntrow[r], 1);
        atomicAdd(&g_degcol[c], 1);
    }
}

// L3: single-block scan of cntrow -> off/cursor, plus dis[] and ppM
__global__ void k_scan_dis(const float* __restrict__ p) {
    const int C = (NN + 1023) / 1024;  // 49 per thread
    __shared__ int part[1024];
    int tid = threadIdx.x;
    int base = tid * C;
    int s = 0;
    for (int k = 0; k < C; k++) {
        int i = base + k;
        s += (i < NN) ? g_cntrow[i] : 0;
    }
    part[tid] = s;
    __syncthreads();
    for (int off = 1; off < 1024; off <<= 1) {
        int t = (tid >= off) ? part[tid - off] : 0;
        __syncthreads();
        part[tid] += t;
        __syncthreads();
    }
    int run = part[tid] - s;  // exclusive prefix of chunk
    for (int k = 0; k < C; k++) {
        int i = base + k;
        if (i < NN) {
            g_off[i] = run;
            g_cursor[i] = run;
            run += g_cntrow[i];
            int dg = g_degcol[i];
            g_dis[i] = (dg > 0) ? rsqrtf((float)dg) : 0.0f;
        }
    }
    if (tid == 1023) g_off[NN] = run;
    if (tid == 0) {
        float pp = 2.0f / (1.0f + __expf(-p[0]));
        g_ppM = make_float2(pp, pp * funord(g_maxbits));
    }
}

// L4: scatter cols — EXACT R2 shape (1 edge/thread, 4B writes)
__global__ void k_scatter(const int* __restrict__ ei) {
    int e = blockIdx.x * blockDim.x + threadIdx.x;
    if (e < EE) {
        int r = ei[e];
        int c = ei[EE + e];
        int pos = atomicAdd(&g_cursor[r], 1);
        g_scol[pos] = c;
    }
}

// L5: EXACT R2 k_main — block (128 threads) per node, unroll 4
__global__ void __launch_bounds__(128) k_main(const float* __restrict__ x,
                                              const float* __restrict__ eps,
                                              float* __restrict__ out) {
    const int r = blockIdx.x;
    const int d = threadIdx.x;
    const int start = g_off[r];
    const int end   = g_off[r + 1];
    const float2 ppM = g_ppM;
    const float pp = ppM.x, M = ppM.y;

    __shared__ int   s_c[128];
    __shared__ float s_w[128];

    float num = 0.0f, den = 0.0f;

    for (int base = start; base < end; base += 128) {
        int j = base + d;
        if (j < end) {
            int c = g_scol[j];
            s_c[d] = c;
            s_w[d] = g_dis[c];
        }
        __syncthreads();
        int m = end - base;
        if (m > 128) m = 128;
        int k = 0;
        for (; k + 4 <= m; k += 4) {
            int   c0 = s_c[k],     c1 = s_c[k + 1], c2 = s_c[k + 2], c3 = s_c[k + 3];
            float w0 = s_w[k],     w1 = s_w[k + 1], w2 = s_w[k + 2], w3 = s_w[k + 3];
            float t0 = __ldg(&x[c0 * DD + d]);
            float t1 = __ldg(&x[c1 * DD + d]);
            float t2 = __ldg(&x[c2 * DD + d]);
            float t3 = __ldg(&x[c3 * DD + d]);
            float s0 = __expf(fmaf(pp, t0, -M));
            float s1 = __expf(fmaf(pp, t1, -M));
            float s2 = __expf(fmaf(pp, t2, -M));
            float s3 = __expf(fmaf(pp, t3, -M));
            den = fmaf(s0, w0, den); num = fmaf(s0 * t0, w0, num);
            den = fmaf(s1, w1, den); num = fmaf(s1 * t1, w1, num);
            den = fmaf(s2, w2, den); num = fmaf(s2 * t2, w2, num);
            den = fmaf(s3, w3, den); num = fmaf(s3 * t3, w3, num);
        }
        for (; k < m; k++) {
            int   c = s_c[k];
            float w = s_w[k];
            float t = __ldg(&x[c * DD + d]);
            float s = __expf(fmaf(pp, t, -M));
            den = fmaf(s, w, den);
            num = fmaf(s * t, w, num);
        }
        __syncthreads();
    }

    float dis_r = g_dis[r];
    float xv = x[r * DD + d];
    float o = __fdividef(dis_r * num, fmaf(dis_r, den, 1e-6f)) + (1.0f + eps[0]) * xv;
    out[r * DD + d] = o;
}

extern "C" void kernel_launch(void* const* d_in, const int* in_sizes, int n_in,
                              void* d_out, int out_size) {
    const float* x   = (const float*)d_in[0];
    const int*   ei  = (const int*)d_in[1];
    const float* eps = (const float*)d_in[2];
    const float* p   = (const float*)d_in[3];
    float* out = (float*)d_out;

    k_zero_max<<<512, 256>>>(x);
    k_count   <<<(EE + 255) / 256, 256>>>(ei);
    k_scan_dis<<<1, 1024>>>(p);
    k_scatter <<<(EE + 255) / 256, 256>>>(ei);
    k_main    <<<NN, 128>>>(x, eps, out);
}

// round 6
// speedup vs baseline: 1.2578x; 1.2578x over previous
#include <cuda_runtime.h>

#define NN 50000
#define DD 128
#define EE 800000

// ---- scratch (__device__ globals: allocation-free) ----
__device__ int   g_degcol[NN];     // degree over col (for norm)
__device__ int   g_cntrow[NN];     // degree over row (for CSR)
__device__ int   g_off[NN + 1];    // CSR row offsets
__device__ int   g_cursor[NN];     // scatter cursors
__device__ int   g_scol[EE];       // edges sorted by row: col ids
__device__ float g_dis[NN];        // deg_col^-0.5 (0 if deg==0)
__device__ unsigned int g_maxbits; // ordered-float max of x
__device__ float2 g_ppM;           // (pp, M = pp*max(x))

// ordered-float encoding for atomicMax on signed floats
__device__ __forceinline__ unsigned int ford(float f) {
    unsigned int b = __float_as_uint(f);
    return (b & 0x80000000u) ? ~b : (b | 0x80000000u);
}
__device__ __forceinline__ float funord(unsigned int u) {
    unsigned int b = (u & 0x80000000u) ? (u & 0x7FFFFFFFu) : ~u;
    return __uint_as_float(b);
}

__global__ void k_init() {
    int i = blockIdx.x * blockDim.x + threadIdx.x;
    if (i < NN) { g_degcol[i] = 0; g_cntrow[i] = 0; }
    if (i == 0) g_maxbits = ford(-3.402823466e38f);
}

__global__ void k_count(const int* __restrict__ ei) {
    int e = blockIdx.x * blockDim.x + threadIdx.x;
    if (e < EE) {
        int r = ei[e];
        int c = ei[EE + e];
        atomicAdd(&g_cntrow[r], 1);
        atomicAdd(&g_degcol[c], 1);
    }
}

__global__ void k_max(const float* __restrict__ x) {
    float m = -3.402823466e38f;
    const float4* x4 = (const float4*)x;
    const int n4 = (NN * DD) / 4;
    for (int i = blockIdx.x * blockDim.x + threadIdx.x; i < n4;
         i += gridDim.x * blockDim.x) {
        float4 v = x4[i];
        m = fmaxf(m, fmaxf(fmaxf(v.x, v.y), fmaxf(v.z, v.w)));
    }
#pragma unroll
    for (int o = 16; o; o >>= 1) m = fmaxf(m, __shfl_xor_sync(~0u, m, o));
    __shared__ float sm[32];
    int lane = threadIdx.x & 31, w = threadIdx.x >> 5;
    if (lane == 0) sm[w] = m;
    __syncthreads();
    if (w == 0) {
        m = (lane < (int)(blockDim.x >> 5)) ? sm[lane] : -3.402823466e38f;
#pragma unroll
        for (int o = 16; o; o >>= 1) m = fmaxf(m, __shfl_xor_sync(~0u, m, o));
        if (lane == 0) atomicMax(&g_maxbits, ford(m));
    }
}

__global__ void k_dis(const float* __restrict__ p) {
    int i = blockIdx.x * blockDim.x + threadIdx.x;
    if (i < NN) {
        int dg = g_degcol[i];
        g_dis[i] = (dg > 0) ? rsqrtf((float)dg) : 0.0f;
    }
    if (i == 0) {
        float pp = 2.0f / (1.0f + __expf(-p[0]));
        float M = pp * funord(g_maxbits);
        g_ppM = make_float2(pp, M);
    }
}

// single-block exclusive scan of g_cntrow -> g_off, g_cursor
__global__ void k_scan() {
    const int C = (NN + 1023) / 1024;  // 49 elems per thread
    __shared__ int part[1024];
    int tid = threadIdx.x;
    int base = tid * C;
    int s = 0;
    for (int k = 0; k < C; k++) {
        int i = base + k;
        s += (i < NN) ? g_cntrow[i] : 0;
    }
    part[tid] = s;
    __syncthreads();
    for (int off = 1; off < 1024; off <<= 1) {
        int t = (tid >= off) ? part[tid - off] : 0;
        __syncthreads();
        part[tid] += t;
        __syncthreads();
    }
    int run = part[tid] - s;  // exclusive prefix of this chunk
    for (int k = 0; k < C; k++) {
        int i = base + k;
        if (i < NN) {
            g_off[i] = run;
            g_cursor[i] = run;
            run += g_cntrow[i];
        }
    }
    if (tid == 1023) g_off[NN] = run;
}

__global__ void k_scatter(const int* __restrict__ ei) {
    int e = blockIdx.x * blockDim.x + threadIdx.x;
    if (e < EE) {
        int r = ei[e];
        int c = ei[EE + e];
        int pos = atomicAdd(&g_cursor[r], 1);
        g_scol[pos] = c;
    }
}

// one block (128 threads) per node r; thread d handles feature d
__global__ void __launch_bounds__(128) k_main(const float* __restrict__ x,
                                              const float* __restrict__ eps,
                                              float* __restrict__ out) {
    const int r = blockIdx.x;
    const int d = threadIdx.x;
    const int start = g_off[r];
    const int end   = g_off[r + 1];
    const float2 ppM = g_ppM;
    const float pp = ppM.x, M = ppM.y;

    __shared__ int   s_c[128];
    __shared__ float s_w[128];

    float num = 0.0f, den = 0.0f;

    for (int base = start; base < end; base += 128) {
        int j = base + d;
        if (j < end) {
            int c = g_scol[j];
            s_c[d] = c;
            s_w[d] = g_dis[c];
        }
        __syncthreads();
        int m = end - base;
        if (m > 128) m = 128;
        int k = 0;
        for (; k + 4 <= m; k += 4) {
            int   c0 = s_c[k],     c1 = s_c[k + 1], c2 = s_c[k + 2], c3 = s_c[k + 3];
            float w0 = s_w[k],     w1 = s_w[k + 1], w2 = s_w[k + 2], w3 = s_w[k + 3];
            float t0 = __ldg(&x[c0 * DD + d]);
            float t1 = __ldg(&x[c1 * DD + d]);
            float t2 = __ldg(&x[c2 * DD + d]);
            float t3 = __ldg(&x[c3 * DD + d]);
            float s0 = __expf(fmaf(pp, t0, -M));
            float s1 = __expf(fmaf(pp, t1, -M));
            float s2 = __expf(fmaf(pp, t2, -M));
            float s3 = __expf(fmaf(pp, t3, -M));
            den = fmaf(s0, w0, den); num = fmaf(s0 * t0, w0, num);
            den = fmaf(s1, w1, den); num = fmaf(s1 * t1, w1, num);
            den = fmaf(s2, w2, den); num = fmaf(s2 * t2, w2, num);
            den = fmaf(s3, w3, den); num = fmaf(s3 * t3, w3, num);
        }
        for (; k < m; k++) {
            int   c = s_c[k];
            float w = s_w[k];
            float t = __ldg(&x[c * DD + d]);
            float s = __expf(fmaf(pp, t, -M));
            den = fmaf(s, w, den);
            num = fmaf(s * t, w, num);
        }
        __syncthreads();
    }

    float dis_r = g_dis[r];
    float xv = x[r * DD + d];
    float o = __fdividef(dis_r * num, fmaf(dis_r, den, 1e-6f)) + (1.0f + eps[0]) * xv;
    out[r * DD + d] = o;
}

extern "C" void kernel_launch(void* const* d_in, const int* in_sizes, int n_in,
                              void* d_out, int out_size) {
    const float* x   = (const float*)d_in[0];
    const int*   ei  = (const int*)d_in[1];
    const float* eps = (const float*)d_in[2];
    const float* p   = (const float*)d_in[3];
    float* out = (float*)d_out;

    k_init   <<<(NN + 255) / 256, 256>>>();
    k_count  <<<(EE + 255) / 256, 256>>>(ei);
    k_max    <<<512, 256>>>(x);
    k_dis    <<<(NN + 255) / 256, 256>>>(p);
    k_scan   <<<1, 1024>>>();
    k_scatter<<<(EE + 255) / 256, 256>>>(ei);
    k_main   <<<NN, 128>>>(x, eps, out);
}

// round 7
// speedup vs baseline: 1.4314x; 1.1380x over previous
#include <cuda_runtime.h>

#define NN 50000
#define DD 128
#define EE 800000

// ---- scratch (__device__ globals: allocation-free) ----
__device__ int   g_degcol[NN];     // degree over col (for norm)
__device__ int   g_cntrow[NN];     // degree over row (for CSR)
__device__ int   g_off[NN + 1];    // CSR row offsets
__device__ int   g_cursor[NN];     // scatter cursors
__device__ int   g_scol[EE];       // edges sorted by row: col ids
__device__ float g_dis[NN];        // deg_col^-0.5 (0 if deg==0)
__device__ unsigned int g_maxbits; // ordered-float max of x
__device__ float2 g_ppM;           // (pp, M = pp*max(x))

// ordered-float encoding for atomicMax on signed floats
__device__ __forceinline__ unsigned int ford(float f) {
    unsigned int b = __float_as_uint(f);
    return (b & 0x80000000u) ? ~b : (b | 0x80000000u);
}
__device__ __forceinline__ float funord(unsigned int u) {
    unsigned int b = (u & 0x80000000u) ? (u & 0x7FFFFFFFu) : ~u;
    return __uint_as_float(b);
}

__global__ void k_init() {
    int i = blockIdx.x * blockDim.x + threadIdx.x;
    if (i < NN) { g_degcol[i] = 0; g_cntrow[i] = 0; }
    if (i == 0) g_maxbits = ford(-3.402823466e38f);
}

__global__ void k_count(const int* __restrict__ ei) {
    int e = blockIdx.x * blockDim.x + threadIdx.x;
    if (e < EE) {
        int r = ei[e];
        int c = ei[EE + e];
        atomicAdd(&g_cntrow[r], 1);
        atomicAdd(&g_degcol[c], 1);
    }
}

__global__ void k_max(const float* __restrict__ x) {
    float m = -3.402823466e38f;
    const float4* x4 = (const float4*)x;
    const int n4 = (NN * DD) / 4;
    for (int i = blockIdx.x * blockDim.x + threadIdx.x; i < n4;
         i += gridDim.x * blockDim.x) {
        float4 v = x4[i];
        m = fmaxf(m, fmaxf(fmaxf(v.x, v.y), fmaxf(v.z, v.w)));
    }
#pragma unroll
    for (int o = 16; o; o >>= 1) m = fmaxf(m, __shfl_xor_sync(~0u, m, o));
    __shared__ float sm[32];
    int lane = threadIdx.x & 31, w = threadIdx.x >> 5;
    if (lane == 0) sm[w] = m;
    __syncthreads();
    if (w == 0) {
        m = (lane < (int)(blockDim.x >> 5)) ? sm[lane] : -3.402823466e38f;
#pragma unroll
        for (int o = 16; o; o >>= 1) m = fmaxf(m, __shfl_xor_sync(~0u, m, o));
        if (lane == 0) atomicMax(&g_maxbits, ford(m));
    }
}

__global__ void k_dis(const float* __restrict__ p) {
    int i = blockIdx.x * blockDim.x + threadIdx.x;
    if (i < NN) {
        int dg = g_degcol[i];
        g_dis[i] = (dg > 0) ? rsqrtf((float)dg) : 0.0f;
    }
    if (i == 0) {
        float pp = 2.0f / (1.0f + __expf(-p[0]));
        float M = pp * funord(g_maxbits);
        g_ppM = make_float2(pp, M);
    }
}

// single-block exclusive scan of g_cntrow -> g_off, g_cursor
__global__ void k_scan() {
    const int C = (NN + 1023) / 1024;  // 49 elems per thread
    __shared__ int part[1024];
    int tid = threadIdx.x;
    int base = tid * C;
    int s = 0;
    for (int k = 0; k < C; k++) {
        int i = base + k;
        s += (i < NN) ? g_cntrow[i] : 0;
    }
    part[tid] = s;
    __syncthreads();
    for (int off = 1; off < 1024; off <<= 1) {
        int t = (tid >= off) ? part[tid - off] : 0;
        __syncthreads();
        part[tid] += t;
        __syncthreads();
    }
    int run = part[tid] - s;  // exclusive prefix of this chunk
    for (int k = 0; k < C; k++) {
        int i = base + k;
        if (i < NN) {
            g_off[i] = run;
            g_cursor[i] = run;
            run += g_cntrow[i];
        }
    }
    if (tid == 1023) g_off[NN] = run;
}

__global__ void k_scatter(const int* __restrict__ ei) {
    int e = blockIdx.x * blockDim.x + threadIdx.x;
    if (e < EE) {
        int r = ei[e];
        int c = ei[EE + e];
        int pos = atomicAdd(&g_cursor[r], 1);
        g_scol[pos] = c;
    }
}

// one block (64 threads) per node r; thread d handles features 2d, 2d+1 (float2)
__global__ void __launch_bounds__(64) k_main(const float* __restrict__ x,
                                             const float* __restrict__ eps,
                                             float* __restrict__ out) {
    const int r = blockIdx.x;
    const int d = threadIdx.x;       // 0..63
    const int start = g_off[r];
    const int end   = g_off[r + 1];
    const float2 ppM = g_ppM;
    const float pp = ppM.x, M = ppM.y;
    const float2* __restrict__ x2 = (const float2*)x;

    __shared__ int   s_c[64];
    __shared__ float s_w[64];

    float2 num = make_float2(0.f, 0.f);
    float2 den = make_float2(0.f, 0.f);

#define EDGE(t, wk)                                                   \
    {                                                                 \
        float sx = __expf(fmaf(pp, (t).x, -M));                       \
        float sy = __expf(fmaf(pp, (t).y, -M));                       \
        den.x = fmaf(sx, (wk), den.x); num.x = fmaf(sx * (t).x, (wk), num.x); \
        den.y = fmaf(sy, (wk), den.y); num.y = fmaf(sy * (t).y, (wk), num.y); \
    }

    for (int base = start; base < end; base += 64) {
        int j = base + d;
        if (j < end) {
            int c = g_scol[j];
            s_c[d] = c;
            s_w[d] = g_dis[c];
        }
        __syncthreads();
        int m = end - base;
        if (m > 64) m = 64;
        int k = 0;
        for (; k + 4 <= m; k += 4) {
            int   c0 = s_c[k],     c1 = s_c[k + 1], c2 = s_c[k + 2], c3 = s_c[k + 3];
            float w0 = s_w[k],     w1 = s_w[k + 1], w2 = s_w[k + 2], w3 = s_w[k + 3];
            float2 t0 = __ldg(&x2[c0 * 64 + d]);
            float2 t1 = __ldg(&x2[c1 * 64 + d]);
            float2 t2 = __ldg(&x2[c2 * 64 + d]);
            float2 t3 = __ldg(&x2[c3 * 64 + d]);
            EDGE(t0, w0) EDGE(t1, w1) EDGE(t2, w2) EDGE(t3, w3)
        }
        for (; k < m; k++) {
            int   c = s_c[k];
            float w = s_w[k];
            float2 t = __ldg(&x2[c * 64 + d]);
            EDGE(t, w)
        }
        __syncthreads();
    }
#undef EDGE

    float dr = g_dis[r];
    float e1 = 1.0f + eps[0];
    float2 xv = __ldg(&x2[r * 64 + d]);
    float2 o;
    o.x = __fdividef(dr * num.x, fmaf(dr, den.x, 1e-6f)) + e1 * xv.x;
    o.y = __fdividef(dr * num.y, fmaf(dr, den.y, 1e-6f)) + e1 * xv.y;
    ((float2*)out)[r * 64 + d] = o;
}

extern "C" void kernel_launch(void* const* d_in, const int* in_sizes, int n_in,
                              void* d_out, int out_size) {
    const float* x   = (const float*)d_in[0];
    const int*   ei  = (const int*)d_in[1];
    const float* eps = (const float*)d_in[2];
    const float* p   = (const float*)d_in[3];
    float* out = (float*)d_out;

    k_init   <<<(NN + 255) / 256, 256>>>();
    k_count  <<<(EE + 255) / 256, 256>>>(ei);
    k_max    <<<512, 256>>>(x);
    k_dis    <<<(NN + 255) / 256, 256>>>(p);
    k_scan   <<<1, 1024>>>();
    k_scatter<<<(EE + 255) / 256, 256>>>(ei);
    k_main   <<<NN, 64>>>(x, eps, out);
}

// round 8
// speedup vs baseline: 1.4835x; 1.0364x over previous
#include <cuda_runtime.h>

#define NN 50000
#define DD 128
#define EE 800000

// ---- scratch (__device__ globals: allocation-free) ----
__device__ int   g_degcol[NN];     // degree over col (for norm)
__device__ int   g_cntrow[NN];     // degree over row (for CSR)
__device__ int   g_off[NN + 1];    // CSR row offsets
__device__ int   g_cursor[NN];     // scatter cursors
__device__ int   g_scol[EE];       // edges sorted by row: col ids
__device__ float g_dis[NN];        // deg_col^-0.5 (0 if deg==0)
__device__ unsigned int g_maxbits; // ordered-float max of x
__device__ float2 g_ppM;           // (pp, M = pp*max(x))

// ordered-float encoding for atomicMax on signed floats
__device__ __forceinline__ unsigned int ford(float f) {
    unsigned int b = __float_as_uint(f);
    return (b & 0x80000000u) ? ~b : (b | 0x80000000u);
}
__device__ __forceinline__ float funord(unsigned int u) {
    unsigned int b = (u & 0x80000000u) ? (u & 0x7FFFFFFFu) : ~u;
    return __uint_as_float(b);
}

__global__ void k_init() {
    int i = blockIdx.x * blockDim.x + threadIdx.x;
    if (i < NN) { g_degcol[i] = 0; g_cntrow[i] = 0; }
    if (i == 0) g_maxbits = ford(-3.402823466e38f);
}

__global__ void k_count(const int* __restrict__ ei) {
    int e = blockIdx.x * blockDim.x + threadIdx.x;
    if (e < EE) {
        int r = ei[e];
        int c = ei[EE + e];
        atomicAdd(&g_cntrow[r], 1);
        atomicAdd(&g_degcol[c], 1);
    }
}

__global__ void k_max(const float* __restrict__ x) {
    float m = -3.402823466e38f;
    const float4* x4 = (const float4*)x;
    const int n4 = (NN * DD) / 4;
    for (int i = blockIdx.x * blockDim.x + threadIdx.x; i < n4;
         i += gridDim.x * blockDim.x) {
        float4 v = x4[i];
        m = fmaxf(m, fmaxf(fmaxf(v.x, v.y), fmaxf(v.z, v.w)));
    }
#pragma unroll
    for (int o = 16; o; o >>= 1) m = fmaxf(m, __shfl_xor_sync(~0u, m, o));
    __shared__ float sm[32];
    int lane = threadIdx.x & 31, w = threadIdx.x >> 5;
    if (lane == 0) sm[w] = m;
    __syncthreads();
    if (w == 0) {
        m = (lane < (int)(blockDim.x >> 5)) ? sm[lane] : -3.402823466e38f;
#pragma unroll
        for (int o = 16; o; o >>= 1) m = fmaxf(m, __shfl_xor_sync(~0u, m, o));
        if (lane == 0) atomicMax(&g_maxbits, ford(m));
    }
}

__global__ void k_dis(const float* __restrict__ p) {
    int i = blockIdx.x * blockDim.x + threadIdx.x;
    if (i < NN) {
        int dg = g_degcol[i];
        g_dis[i] = (dg > 0) ? rsqrtf((float)dg) : 0.0f;
    }
    if (i == 0) {
        float pp = 2.0f / (1.0f + __expf(-p[0]));
        float M = pp * funord(g_maxbits);
        g_ppM = make_float2(pp, M);
    }
}

// single-block exclusive scan of g_cntrow -> g_off, g_cursor
__global__ void k_scan() {
    const int C = (NN + 1023) / 1024;  // 49 elems per thread
    __shared__ int part[1024];
    int tid = threadIdx.x;
    int base = tid * C;
    int s = 0;
    for (int k = 0; k < C; k++) {
        int i = base + k;
        s += (i < NN) ? g_cntrow[i] : 0;
    }
    part[tid] = s;
    __syncthreads();
    for (int off = 1; off < 1024; off <<= 1) {
        int t = (tid >= off) ? part[tid - off] : 0;
        __syncthreads();
        part[tid] += t;
        __syncthreads();
    }
    int run = part[tid] - s;  // exclusive prefix of this chunk
    for (int k = 0; k < C; k++) {
        int i = base + k;
        if (i < NN) {
            g_off[i] = run;
            g_cursor[i] = run;
            run += g_cntrow[i];
        }
    }
    if (tid == 1023) g_off[NN] = run;
}

__global__ void k_scatter(const int* __restrict__ ei) {
    int e = blockIdx.x * blockDim.x + threadIdx.x;
    if (e < EE) {
        int r = ei[e];
        int c = ei[EE + e];
        int pos = atomicAdd(&g_cursor[r], 1);
        g_scol[pos] = c;
    }
}

// 64-thread block = 2 independent warps, each warp handles one node.
// Lane l owns features 4l..4l+3 (one LDG.128 per edge).
__global__ void __launch_bounds__(64) k_main(const float* __restrict__ x,
                                             const float* __restrict__ eps,
                                             float* __restrict__ out) {
    const int w    = threadIdx.x >> 5;             // warp in block: 0/1
    const int lane = threadIdx.x & 31;
    const int r    = blockIdx.x * 2 + w;
    if (r >= NN) return;
    const int start = g_off[r];
    const int end   = g_off[r + 1];
    const float2 ppM = g_ppM;
    const float pp = ppM.x, M = ppM.y;
    const float4* __restrict__ x4 = (const float4*)x;

    __shared__ int   s_c[64];
    __shared__ float s_w[64];
    int*   sc = s_c + w * 32;
    float* sw = s_w + w * 32;

    float4 num = make_float4(0.f, 0.f, 0.f, 0.f);
    float4 den = make_float4(0.f, 0.f, 0.f, 0.f);

#define EDGE(t, wk)                                                   \
    {                                                                 \
        float ex = __expf(fmaf(pp, (t).x, -M));                       \
        float ey = __expf(fmaf(pp, (t).y, -M));                       \
        float ez = __expf(fmaf(pp, (t).z, -M));                       \
        float ew = __expf(fmaf(pp, (t).w, -M));                       \
        den.x = fmaf(ex, (wk), den.x); num.x = fmaf(ex * (t).x, (wk), num.x); \
        den.y = fmaf(ey, (wk), den.y); num.y = fmaf(ey * (t).y, (wk), num.y); \
        den.z = fmaf(ez, (wk), den.z); num.z = fmaf(ez * (t).z, (wk), num.z); \
        den.w = fmaf(ew, (wk), den.w); num.w = fmaf(ew * (t).w, (wk), num.w); \
    }

    for (int base = start; base < end; base += 32) {
        int j = base + lane;
        if (j < end) {
            int c = g_scol[j];
            sc[lane] = c;
            sw[lane] = g_dis[c];
        }
        __syncwarp();
        int m = end - base;
        if (m > 32) m = 32;
        int k = 0;
        for (; k + 4 <= m; k += 4) {
            int   c0 = sc[k],     c1 = sc[k + 1], c2 = sc[k + 2], c3 = sc[k + 3];
            float w0 = sw[k],     w1 = sw[k + 1], w2 = sw[k + 2], w3 = sw[k + 3];
            float4 t0 = __ldg(&x4[c0 * 32 + lane]);
            float4 t1 = __ldg(&x4[c1 * 32 + lane]);
            float4 t2 = __ldg(&x4[c2 * 32 + lane]);
            float4 t3 = __ldg(&x4[c3 * 32 + lane]);
            EDGE(t0, w0) EDGE(t1, w1) EDGE(t2, w2) EDGE(t3, w3)
        }
        for (; k < m; k++) {
            int   c = sc[k];
            float wk = sw[k];
            float4 t = __ldg(&x4[c * 32 + lane]);
            EDGE(t, wk)
        }
        __syncwarp();
    }
#undef EDGE

    float dr = g_dis[r];
    float e1 = 1.0f + eps[0];
    float4 xv = __ldg(&x4[r * 32 + lane]);
    float4 o;
    o.x = __fdividef(dr * num.x, fmaf(dr, den.x, 1e-6f)) + e1 * xv.x;
    o.y = __fdividef(dr * num.y, fmaf(dr, den.y, 1e-6f)) + e1 * xv.y;
    o.z = __fdividef(dr * num.z, fmaf(dr, den.z, 1e-6f)) + e1 * xv.z;
    o.w = __fdividef(dr * num.w, fmaf(dr, den.w, 1e-6f)) + e1 * xv.w;
    ((float4*)out)[r * 32 + lane] = o;
}

extern "C" void kernel_launch(void* const* d_in, const int* in_sizes, int n_in,
                              void* d_out, int out_size) {
    const float* x   = (const float*)d_in[0];
    const int*   ei  = (const int*)d_in[1];
    const float* eps = (const float*)d_in[2];
    const float* p   = (const float*)d_in[3];
    float* out = (float*)d_out;

    k_init   <<<(NN + 255) / 256, 256>>>();
    k_count  <<<(EE + 255) / 256, 256>>>(ei);
    k_max    <<<512, 256>>>(x);
    k_dis    <<<(NN + 255) / 256, 256>>>(p);
    k_scan   <<<1, 1024>>>();
    k_scatter<<<(EE + 255) / 256, 256>>>(ei);
    k_main   <<<(NN + 1) / 2, 64>>>(x, eps, out);
}

// round 9
// speedup vs baseline: 1.5291x; 1.0307x over previous
#include <cuda_runtime.h>

#define NN 50000
#define DD 128
#define EE 800000

// ---- scratch (__device__ globals: allocation-free) ----
__device__ int   g_degcol[NN];     // degree over col (for norm)
__device__ int   g_cntrow[NN];     // degree over row (for CSR)
__device__ int   g_off[NN + 1];    // CSR row offsets
__device__ int   g_cursor[NN];     // scatter cursors
__device__ int   g_scol[EE];       // edges sorted by row: col ids
__device__ float g_dis[NN];        // deg_col^-0.5 (0 if deg==0)
__device__ unsigned int g_maxbits; // ordered-float max of x
__device__ float2 g_ppM;           // (pp*log2e, pp*max(x)*log2e) -- EX2-prefolded

// ordered-float encoding for atomicMax on signed floats
__device__ __forceinline__ unsigned int ford(float f) {
    unsigned int b = __float_as_uint(f);
    return (b & 0x80000000u) ? ~b : (b | 0x80000000u);
}
__device__ __forceinline__ float funord(unsigned int u) {
    unsigned int b = (u & 0x80000000u) ? (u & 0x7FFFFFFFu) : ~u;
    return __uint_as_float(b);
}
__device__ __forceinline__ float ex2(float z) {
    float r;
    asm("ex2.approx.f32 %0, %1;" : "=f"(r) : "f"(z));
    return r;
}

__global__ void k_init() {
    int i = blockIdx.x * blockDim.x + threadIdx.x;
    if (i < NN) { g_degcol[i] = 0; g_cntrow[i] = 0; }
    if (i == 0) g_maxbits = ford(-3.402823466e38f);
}

// L2: degree histograms (edge-parallel) + global max of x (grid-stride).
// The max loop's work fills issue slots otherwise idle behind atomic latency.
__global__ void k_count_max(const int* __restrict__ ei,
                            const float* __restrict__ x) {
    int e = blockIdx.x * blockDim.x + threadIdx.x;
    if (e < EE) {
        atomicAdd(&g_cntrow[ei[e]], 1);
        atomicAdd(&g_degcol[ei[EE + e]], 1);
    }

    float m = -3.402823466e38f;
    const float4* x4 = (const float4*)x;
    const int n4 = (NN * DD) / 4;
    const int gsz = gridDim.x * blockDim.x;
    for (int i = e; i < n4; i += gsz) {
        float4 v = x4[i];
        m = fmaxf(m, fmaxf(fmaxf(v.x, v.y), fmaxf(v.z, v.w)));
    }
#pragma unroll
    for (int o = 16; o; o >>= 1) m = fmaxf(m, __shfl_xor_sync(~0u, m, o));
    __shared__ float sm[32];
    int lane = threadIdx.x & 31, w = threadIdx.x >> 5;
    if (lane == 0) sm[w] = m;
    __syncthreads();
    if (w == 0) {
        m = (lane < (int)(blockDim.x >> 5)) ? sm[lane] : -3.402823466e38f;
#pragma unroll
        for (int o = 16; o; o >>= 1) m = fmaxf(m, __shfl_xor_sync(~0u, m, o));
        if (lane == 0) atomicMax(&g_maxbits, ford(m));
    }
}

// single-block exclusive scan of g_cntrow -> g_off, g_cursor
__global__ void k_scan() {
    const int C = (NN + 1023) / 1024;  // 49 elems per thread
    __shared__ int part[1024];
    int tid = threadIdx.x;
    int base = tid * C;
    int s = 0;
    for (int k = 0; k < C; k++) {
        int i = base + k;
        s += (i < NN) ? g_cntrow[i] : 0;
    }
    part[tid] = s;
    __syncthreads();
    for (int off = 1; off < 1024; off <<= 1) {
        int t = (tid >= off) ? part[tid - off] : 0;
        __syncthreads();
        part[tid] += t;
        __syncthreads();
    }
    int run = part[tid] - s;  // exclusive prefix of this chunk
    for (int k = 0; k < C; k++) {
        int i = base + k;
        if (i < NN) {
            g_off[i] = run;
            g_cursor[i] = run;
            run += g_cntrow[i];
        }
    }
    if (tid == 1023) g_off[NN] = run;
}

// L4: scatter cols into row-sorted order (edge-parallel) + dis[] for first
// NN threads + ppM on thread 0. Extra work hides behind atomic latency.
__global__ void k_scatter_dis(const int* __restrict__ ei,
                              const float* __restrict__ p) {
    int e = blockIdx.x * blockDim.x + threadIdx.x;
    if (e < EE) {
        int r = ei[e];
        int c = ei[EE + e];
        int pos = atomicAdd(&g_cursor[r], 1);
        g_scol[pos] = c;
    }
    if (e < NN) {
        int dg = g_degcol[e];
        g_dis[e] = (dg > 0) ? rsqrtf((float)dg) : 0.0f;
    }
    if (e == 0) {
        const float LOG2E = 1.44269504088896340736f;
        float pp = 2.0f / (1.0f + __expf(-p[0]));
        float M = pp * funord(g_maxbits);
        g_ppM = make_float2(pp * LOG2E, M * LOG2E);
    }
}

// 64-thread block = 2 independent warps, each warp handles one node.
// Lane l owns features 4l..4l+3 (one LDG.128 per edge).
__global__ void __launch_bounds__(64) k_main(const float* __restrict__ x,
                                             const float* __restrict__ eps,
                                             float* __restrict__ out) {
    const int w    = threadIdx.x >> 5;             // warp in block: 0/1
    const int lane = threadIdx.x & 31;
    const int r    = blockIdx.x * 2 + w;
    if (r >= NN) return;
    const int start = g_off[r];
    const int end   = g_off[r + 1];
    const float2 ppM = g_ppM;
    const float pp2 = ppM.x, M2 = ppM.y;   // EX2-prefolded
    const float4* __restrict__ x4 = (const float4*)x;

    __shared__ int   s_c[64];
    __shared__ float s_w[64];
    int*   sc = s_c + w * 32;
    float* sw = s_w + w * 32;

    float4 num = make_float4(0.f, 0.f, 0.f, 0.f);
    float4 den = make_float4(0.f, 0.f, 0.f, 0.f);

#define EDGE(t, wk)                                                   \
    {                                                                 \
        float ax = ex2(fmaf(pp2, (t).x, -M2)) * (wk);                 \
        float ay = ex2(fmaf(pp2, (t).y, -M2)) * (wk);                 \
        float az = ex2(fmaf(pp2, (t).z, -M2)) * (wk);                 \
        float aw = ex2(fmaf(pp2, (t).w, -M2)) * (wk);                 \
        den.x += ax; num.x = fmaf(ax, (t).x, num.x);                  \
        den.y += ay; num.y = fmaf(ay, (t).y, num.y);                  \
        den.z += az; num.z = fmaf(az, (t).z, num.z);                  \
        den.w += aw; num.w = fmaf(aw, (t).w, num.w);                  \
    }

    for (int base = start; base < end; base += 32) {
        int j = base + lane;
        if (j < end) {
            int c = g_scol[j];
            sc[lane] = c;
            sw[lane] = g_dis[c];
        }
        __syncwarp();
        int m = end - base;
        if (m > 32) m = 32;
        int k = 0;
        for (; k + 4 <= m; k += 4) {
            int   c0 = sc[k],     c1 = sc[k + 1], c2 = sc[k + 2], c3 = sc[k + 3];
            float w0 = sw[k],     w1 = sw[k + 1], w2 = sw[k + 2], w3 = sw[k + 3];
            float4 t0 = __ldg(&x4[c0 * 32 + lane]);
            float4 t1 = __ldg(&x4[c1 * 32 + lane]);
            float4 t2 = __ldg(&x4[c2 * 32 + lane]);
            float4 t3 = __ldg(&x4[c3 * 32 + lane]);
            EDGE(t0, w0) EDGE(t1, w1) EDGE(t2, w2) EDGE(t3, w3)
        }
        for (; k < m; k++) {
            int   c = sc[k];
            float wk = sw[k];
            float4 t = __ldg(&x4[c * 32 + lane]);
            EDGE(t, wk)
        }
        __syncwarp();
    }
#undef EDGE

    float dr = g_dis[r];
    float e1 = 1.0f + eps[0];
    float4 xv = __ldg(&x4[r * 32 + lane]);
    float4 o;
    o.x = __fdividef(dr * num.x, fmaf(dr, den.x, 1e-6f)) + e1 * xv.x;
    o.y = __fdividef(dr * num.y, fmaf(dr, den.y, 1e-6f)) + e1 * xv.y;
    o.z = __fdividef(dr * num.z, fmaf(dr, den.z, 1e-6f)) + e1 * xv.z;
    o.w = __fdividef(dr * num.w, fmaf(dr, den.w, 1e-6f)) + e1 * xv.w;
    ((float4*)out)[r * 32 + lane] = o;
}

extern "C" void kernel_launch(void* const* d_in, const int* in_sizes, int n_in,
                              void* d_out, int out_size) {
    const float* x   = (const float*)d_in[0];
    const int*   ei  = (const int*)d_in[1];
    const float* eps = (const float*)d_in[2];
    const float* p   = (const float*)d_in[3];
    float* out = (float*)d_out;

    k_init       <<<(NN + 255) / 256, 256>>>();
    k_count_max  <<<(EE + 255) / 256, 256>>>(ei, x);
    k_scan       <<<1, 1024>>>();
    k_scatter_dis<<<(EE + 255) / 256, 256>>>(ei, p);
    k_main       <<<(NN + 1) / 2, 64>>>(x, eps, out);
}